// round 3
// baseline (speedup 1.0000x reference)
#include <cuda_runtime.h>

// Problem constants
#define BB   64      // batch
#define L0   128     // input length
#define C0   16      // input channels
#define L1C  124     // len after block1
#define CH1  128     // channels after block1
#define L2C  120     // len after block2
#define CH2  1024    // channels after block2
#define L3C  116     // len after block3
#define CH3  8192    // channels after block3

#define NSLICE 16
#define LCHUNK 29            // 4 chunks x 29 = 116
#define NLC 4
#define FUSED_BLOCKS (64 * NLC * 8)   // grid.x * grid.y * grid.z = 2048

// Scratch (device globals; no runtime allocation allowed)
__device__ float g_out1[BB * L1C * CH1];   // [b][l][ch1]  ~4 MB
__device__ float g_acc [NSLICE][BB * 2];   // sliced dense accumulators
__device__ unsigned g_count;               // completed-block counter

// ---------------------------------------------------------------------------
// Packed f32x2 helpers (sm_103a FFMA2 — PTX-only)
typedef unsigned long long ull;

__device__ __forceinline__ ull pack2(float lo, float hi) {
    ull d; asm("mov.b64 %0, {%1, %2};" : "=l"(d) : "f"(lo), "f"(hi));
    return d;
}
__device__ __forceinline__ void unpack2(ull d, float& lo, float& hi) {
    asm("mov.b64 {%0, %1}, %2;" : "=f"(lo), "=f"(hi) : "l"(d));
}
__device__ __forceinline__ ull fma2(ull a, ull b, ull c) {
    ull d; asm("fma.rn.f32x2 %0, %1, %2, %3;" : "=l"(d) : "l"(a), "l"(b), "l"(c));
    return d;
}
__device__ __forceinline__ ull relu2(ull x) {
    float lo, hi; unpack2(x, lo, hi);
    return pack2(fmaxf(lo, 0.f), fmaxf(hi, 0.f));
}

// ---------------------------------------------------------------------------
// Block1 (+ accumulator zeroing for this launch's fused pass):
// out1[b,l,o] = relu(sum_k state[b,l+k,o/8] * k1[k,o] + b1[o])
__global__ void block1_kernel(const float* __restrict__ state,
                              const float* __restrict__ k1w,
                              const float* __restrict__ b1) {
    int idx = blockIdx.x * blockDim.x + threadIdx.x;
    if (idx < NSLICE * BB * 2) ((float*)g_acc)[idx] = 0.f;
    if (idx == 0) g_count = 0u;
    if (idx >= BB * L1C * CH1) return;
    int o = idx & (CH1 - 1);
    int l = (idx >> 7) % L1C;
    int b = idx / (L1C * CH1);
    int c = o >> 3;
    const float* sp = state + (b * L0 + l) * C0 + c;
    float v = b1[o];
#pragma unroll
    for (int k = 0; k < 5; k++) v = fmaf(sp[k * C0], k1w[k * CH1 + o], v);
    g_out1[idx] = fmaxf(v, 0.f);
}

// ---------------------------------------------------------------------------
// Fused block2 + block3 + dense + (last block) finalize.
// Lane = (cl 0..15 -> channel, fh 0..1 -> filter half). Each thread packs a
// batch PAIR into f32x2: recomputes x2 via FFMA2, conv3 via FFMA2, relu+dense
// scalar. Warp shfl-reduces (16 c x 8 f) and atomically adds into a slice.
// Grid: x = 64 c-tiles, y = 4 l-chunks (29 each), z = 8; block = 128 (4 warps
// = 4 batch pairs). Last finished block sums slices, applies bias+tanh.
__global__ void __launch_bounds__(128, 5)
fused23_kernel(const float* __restrict__ k2w, const float* __restrict__ b2,
               const float* __restrict__ k3w, const float* __restrict__ b3,
               const float* __restrict__ W,   const float* __restrict__ bd,
               float* __restrict__ out) {
    int tid = threadIdx.x;
    int cl  = tid & 15;
    int fh  = (tid >> 4) & 1;
    int wg  = tid >> 5;                     // warp 0..3
    int ct  = blockIdx.x;                   // 0..63
    int c   = ct * 16 + cl;                 // 0..1023
    int c1  = c >> 3;                       // out1 channel
    int l0  = blockIdx.y * LCHUNK;
    int l1  = min(L3C, l0 + LCHUNK);
    int b0  = (blockIdx.z * 4 + wg) * 2;    // batch pair (b0, b0+1)

    // Block2 weights (packed duplicate) for channel c
    ull w2p[5];
#pragma unroll
    for (int k = 0; k < 5; k++) { float w = k2w[k * CH2 + c]; w2p[k] = pack2(w, w); }
    ull bias2p; { float bv = b2[c]; bias2p = pack2(bv, bv); }

    // Block3 weights (packed duplicate) for filters fh*4..fh*4+3
    ull w3p[5][4], bias3p[4];
#pragma unroll
    for (int k = 0; k < 5; k++)
#pragma unroll
        for (int f = 0; f < 4; f++) {
            float w = k3w[k * CH3 + c * 8 + fh * 4 + f];
            w3p[k][f] = pack2(w, w);
        }
#pragma unroll
    for (int f = 0; f < 4; f++) { float bv = b3[c * 8 + fh * 4 + f]; bias3p[f] = pack2(bv, bv); }

    const float* p0 = g_out1 + ((size_t)b0 * L1C) * CH1 + c1;
    const float* p1 = p0 + L1C * CH1;

    // Init rolling windows. Invariant at iteration l:
    //   xwp[k] = x2(b pair, l+k, c)      k=0..4   (packed)
    //   owp[k] = out1(b pair, l+4+k, c1) k=0..4   (packed)
    ull owp[5], xwp[5];
    {
        ull o[9];
#pragma unroll
        for (int k = 0; k < 9; k++)
            o[k] = pack2(p0[(l0 + k) * CH1], p1[(l0 + k) * CH1]);
#pragma unroll
        for (int k = 0; k < 5; k++) {
            ull v = bias2p;
#pragma unroll
            for (int q = 0; q < 5; q++) v = fma2(o[k + q], w2p[q], v);
            xwp[k] = relu2(v);
        }
#pragma unroll
        for (int k = 0; k < 5; k++) owp[k] = o[4 + k];
    }

    float a00 = 0.f, a01 = 0.f, a10 = 0.f, a11 = 0.f;  // [batch][col]

    for (int l = l0; l < l1; l++) {
        // Dense weights for (l, c, fh*4..+3) x cols{0,1}: 8 floats
        const float4* Wp = (const float4*)(W + ((size_t)l * CH3 + c * 8 + fh * 4) * 2);
        float4 A = Wp[0], Bv = Wp[1];
        float wf[8] = {A.x, A.y, A.z, A.w, Bv.x, Bv.y, Bv.z, Bv.w};
#pragma unroll
        for (int f = 0; f < 4; f++) {
            ull vp = bias3p[f];
#pragma unroll
            for (int k = 0; k < 5; k++) vp = fma2(xwp[k], w3p[k][f], vp);
            float va, vb; unpack2(vp, va, vb);
            va = fmaxf(va, 0.f); vb = fmaxf(vb, 0.f);
            float wc0 = wf[2 * f], wc1 = wf[2 * f + 1];
            a00 = fmaf(va, wc0, a00); a01 = fmaf(va, wc1, a01);
            a10 = fmaf(vb, wc0, a10); a11 = fmaf(vb, wc1, a11);
        }
        if (l + 1 < l1) {
            ull no = pack2(p0[(l + 9) * CH1], p1[(l + 9) * CH1]);
#pragma unroll
            for (int k = 0; k < 4; k++) owp[k] = owp[k + 1];
            owp[4] = no;
            ull v = bias2p;
#pragma unroll
            for (int k = 0; k < 5; k++) v = fma2(owp[k], w2p[k], v);
#pragma unroll
            for (int k = 0; k < 4; k++) xwp[k] = xwp[k + 1];
            xwp[4] = relu2(v);
        }
    }

    // Warp reduction over 32 lanes (16 c-lanes x 2 filter halves)
#pragma unroll
    for (int s = 16; s > 0; s >>= 1) {
        a00 += __shfl_xor_sync(0xFFFFFFFFu, a00, s);
        a01 += __shfl_xor_sync(0xFFFFFFFFu, a01, s);
        a10 += __shfl_xor_sync(0xFFFFFFFFu, a10, s);
        a11 += __shfl_xor_sync(0xFFFFFFFFu, a11, s);
    }
    if ((tid & 31) == 0) {
        int sl = ct & (NSLICE - 1);
        atomicAdd(&g_acc[sl][b0 * 2],     a00);
        atomicAdd(&g_acc[sl][b0 * 2 + 1], a01);
        atomicAdd(&g_acc[sl][b0 * 2 + 2], a10);
        atomicAdd(&g_acc[sl][b0 * 2 + 3], a11);
    }

    // Last block finalizes (threadfence reduction pattern)
    __shared__ bool s_last;
    __threadfence();
    __syncthreads();
    if (tid == 0) s_last = (atomicAdd(&g_count, 1u) == FUSED_BLOCKS - 1u);
    __syncthreads();
    if (s_last) {
        __threadfence();
        int i = tid;  // 128 threads == 128 outputs
        volatile float* ga = (volatile float*)g_acc;
        float v = 0.f;
#pragma unroll
        for (int s = 0; s < NSLICE; s++) v += ga[s * BB * 2 + i];
        out[i] = tanhf(v + bd[i & 1]);
    }
}

// ---------------------------------------------------------------------------
extern "C" void kernel_launch(void* const* d_in, const int* in_sizes, int n_in,
                              void* d_out, int out_size) {
    const float* state = (const float*)d_in[0];
    const float* k1w   = (const float*)d_in[1];
    const float* b1    = (const float*)d_in[2];
    const float* k2w   = (const float*)d_in[3];
    const float* b2    = (const float*)d_in[4];
    const float* k3w   = (const float*)d_in[5];
    const float* b3    = (const float*)d_in[6];
    const float* W     = (const float*)d_in[7];
    const float* bd    = (const float*)d_in[8];
    float* out = (float*)d_out;

    block1_kernel<<<(BB * L1C * CH1 + 255) / 256, 256>>>(state, k1w, b1);
    fused23_kernel<<<dim3(64, NLC, 8), 128>>>(k2w, b2, k3w, b3, W, bd, out);
}

// round 4
// speedup vs baseline: 1.1688x; 1.1688x over previous
#include <cuda_runtime.h>

// Problem constants
#define BB   64      // batch
#define L0   128     // input length
#define C0   16      // input channels
#define L1C  124     // len after block1
#define CH1  128     // channels after block1
#define L2C  120     // len after block2
#define CH2  1024    // channels after block2
#define L3C  116     // len after block3
#define CH3  8192    // channels after block3

#define NSLICE 16
#define LCHUNK 20
#define NLC 6                           // chunks: 5x20 + 1x16 = 116
#define ZB  4                           // batch groups (16 b each)
#define FUSED_BLOCKS (64 * NLC * ZB)    // 1536

// Scratch (device globals; no runtime allocation allowed)
__device__ float g_out1[BB * L1C * CH1];   // [b][l][ch1]  ~4 MB
__device__ float g_acc [NSLICE][BB * 2];   // sliced dense accumulators
__device__ unsigned g_count;               // completed-block counter

// ---------------------------------------------------------------------------
// Packed f32x2 helpers (sm_103a FFMA2 — PTX-only)
typedef unsigned long long ull;

__device__ __forceinline__ ull pack2(float lo, float hi) {
    ull d; asm("mov.b64 %0, {%1, %2};" : "=l"(d) : "f"(lo), "f"(hi));
    return d;
}
__device__ __forceinline__ void unpack2(ull d, float& lo, float& hi) {
    asm("mov.b64 {%0, %1}, %2;" : "=f"(lo), "=f"(hi) : "l"(d));
}
__device__ __forceinline__ ull fma2(ull a, ull b, ull c) {
    ull d; asm("fma.rn.f32x2 %0, %1, %2, %3;" : "=l"(d) : "l"(a), "l"(b), "l"(c));
    return d;
}
__device__ __forceinline__ ull relu2(ull x) {
    float lo, hi; unpack2(x, lo, hi);
    return pack2(fmaxf(lo, 0.f), fmaxf(hi, 0.f));
}

// ---------------------------------------------------------------------------
// Block1 (+ zero accumulators/counter for the fused pass)
__global__ void block1_kernel(const float* __restrict__ state,
                              const float* __restrict__ k1w,
                              const float* __restrict__ b1) {
    int idx = blockIdx.x * blockDim.x + threadIdx.x;
    if (idx < NSLICE * BB * 2) ((float*)g_acc)[idx] = 0.f;
    if (idx == 0) g_count = 0u;
    if (idx >= BB * L1C * CH1) return;
    int o = idx & (CH1 - 1);
    int l = (idx >> 7) % L1C;
    int b = idx / (L1C * CH1);
    int c = o >> 3;
    const float* sp = state + (b * L0 + l) * C0 + c;
    float v = b1[o];
#pragma unroll
    for (int k = 0; k < 5; k++) v = fmaf(sp[k * C0], k1w[k * CH1 + o], v);
    g_out1[idx] = fmaxf(v, 0.f);
}

// ---------------------------------------------------------------------------
// Fused block2 + block3 + dense + (last block) finalize.
// Lane = (cl 0..15 -> channel, fh 0..1 -> filter half). Each thread carries
// TWO packed batch-pairs (4 batches): rolling out1 window -> recompute x2
// (FFMA2) -> conv3 (FFMA2) -> relu + dense contraction (scalar).
// Warp shfl-reduces (16 c x 8 f); lane 0 atomically adds into a slice.
// Grid: x = 64 c-tiles, y = 6 l-chunks (20), z = 4 batch groups; block = 128
// (4 warps x 4 batches = 16 batches). Last block sums slices + bias + tanh.
__global__ void __launch_bounds__(128, 4)
fused23_kernel(const float* __restrict__ k2w, const float* __restrict__ b2,
               const float* __restrict__ k3w, const float* __restrict__ b3,
               const float* __restrict__ W,   const float* __restrict__ bd,
               float* __restrict__ out) {
    int tid = threadIdx.x;
    int cl  = tid & 15;
    int fh  = (tid >> 4) & 1;
    int wg  = tid >> 5;                     // warp 0..3
    int ct  = blockIdx.x;                   // 0..63
    int c   = ct * 16 + cl;                 // 0..1023
    int c1  = c >> 3;                       // out1 channel
    int l0  = blockIdx.y * LCHUNK;
    int l1  = min(L3C, l0 + LCHUNK);
    int b0  = (blockIdx.z * 4 + wg) * 4;    // batches b0..b0+3

    // Block2 weights (packed duplicate) for channel c
    ull w2p[5];
#pragma unroll
    for (int k = 0; k < 5; k++) { float w = k2w[k * CH2 + c]; w2p[k] = pack2(w, w); }
    ull bias2p; { float bv = b2[c]; bias2p = pack2(bv, bv); }

    // Block3 weights (packed duplicate) for filters fh*4..fh*4+3
    ull w3p[5][4], bias3p[4];
#pragma unroll
    for (int k = 0; k < 5; k++)
#pragma unroll
        for (int f = 0; f < 4; f++) {
            float w = k3w[k * CH3 + c * 8 + fh * 4 + f];
            w3p[k][f] = pack2(w, w);
        }
#pragma unroll
    for (int f = 0; f < 4; f++) { float bv = b3[c * 8 + fh * 4 + f]; bias3p[f] = pack2(bv, bv); }

    const float* pB[4];
#pragma unroll
    for (int j = 0; j < 4; j++)
        pB[j] = g_out1 + ((size_t)(b0 + j) * L1C) * CH1 + c1;

    // Rolling windows, two packed pairs. Invariant entering iteration l:
    //   xwp[p][k] = x2(pair p, l+k, c)      k=0..4
    //   owp[p][k] = out1(pair p, l+4+k, c1) k=0..4
    ull owp[2][5], xwp[2][5];
#pragma unroll
    for (int p = 0; p < 2; p++) {
        const float* q0 = pB[2 * p];
        const float* q1 = pB[2 * p + 1];
        ull o[9];
#pragma unroll
        for (int k = 0; k < 9; k++)
            o[k] = pack2(q0[(l0 + k) * CH1], q1[(l0 + k) * CH1]);
#pragma unroll
        for (int k = 0; k < 5; k++) {
            ull v = bias2p;
#pragma unroll
            for (int q = 0; q < 5; q++) v = fma2(o[k + q], w2p[q], v);
            xwp[p][k] = relu2(v);
        }
#pragma unroll
        for (int k = 0; k < 5; k++) owp[p][k] = o[4 + k];
    }

    // acc[pair][half][col]: half 0 = first batch of pair, 1 = second
    float acc[2][2][2] = {};

#pragma unroll 5
    for (int l = l0; l < l1; l++) {
        // Dense weights for (l, c, filters fh*4..+3), cols {0,1}: 8 floats
        const float4* Wp =
            (const float4*)(W + ((size_t)l * CH3 + c * 8 + fh * 4) * 2);
        float4 A = Wp[0], Bv = Wp[1];
        float wf[8] = {A.x, A.y, A.z, A.w, Bv.x, Bv.y, Bv.z, Bv.w};
#pragma unroll
        for (int p = 0; p < 2; p++) {
#pragma unroll
            for (int f = 0; f < 4; f++) {
                ull vp = bias3p[f];
#pragma unroll
                for (int k = 0; k < 5; k++) vp = fma2(xwp[p][k], w3p[k][f], vp);
                float va, vb; unpack2(vp, va, vb);
                va = fmaxf(va, 0.f); vb = fmaxf(vb, 0.f);
                float wc0 = wf[2 * f], wc1 = wf[2 * f + 1];
                acc[p][0][0] = fmaf(va, wc0, acc[p][0][0]);
                acc[p][0][1] = fmaf(va, wc1, acc[p][0][1]);
                acc[p][1][0] = fmaf(vb, wc0, acc[p][1][0]);
                acc[p][1][1] = fmaf(vb, wc1, acc[p][1][1]);
            }
        }
        if (l + 1 < l1) {
#pragma unroll
            for (int p = 0; p < 2; p++) {
                ull no = pack2(pB[2 * p][(l + 9) * CH1],
                               pB[2 * p + 1][(l + 9) * CH1]);
#pragma unroll
                for (int k = 0; k < 4; k++) owp[p][k] = owp[p][k + 1];
                owp[p][4] = no;
                ull v = bias2p;
#pragma unroll
                for (int k = 0; k < 5; k++) v = fma2(owp[p][k], w2p[k], v);
#pragma unroll
                for (int k = 0; k < 4; k++) xwp[p][k] = xwp[p][k + 1];
                xwp[p][4] = relu2(v);
            }
        }
    }

    // Warp reduction over 32 lanes (16 c x 2 fh) for each of 4 batches x 2 cols
#pragma unroll
    for (int p = 0; p < 2; p++)
#pragma unroll
        for (int h = 0; h < 2; h++)
#pragma unroll
            for (int col = 0; col < 2; col++) {
                float v = acc[p][h][col];
#pragma unroll
                for (int s = 16; s > 0; s >>= 1)
                    v += __shfl_xor_sync(0xFFFFFFFFu, v, s);
                if ((tid & 31) == 0)
                    atomicAdd(&g_acc[ct & (NSLICE - 1)]
                                    [(b0 + 2 * p + h) * 2 + col], v);
            }

    // Last block finalizes (threadfence reduction pattern)
    __shared__ bool s_last;
    __threadfence();
    __syncthreads();
    if (tid == 0) s_last = (atomicAdd(&g_count, 1u) == FUSED_BLOCKS - 1u);
    __syncthreads();
    if (s_last) {
        __threadfence();
        int i = tid;  // 128 threads == 128 outputs
        volatile float* ga = (volatile float*)g_acc;
        float v = 0.f;
#pragma unroll
        for (int s = 0; s < NSLICE; s++) v += ga[s * BB * 2 + i];
        out[i] = tanhf(v + bd[i & 1]);
    }
}

// ---------------------------------------------------------------------------
extern "C" void kernel_launch(void* const* d_in, const int* in_sizes, int n_in,
                              void* d_out, int out_size) {
    const float* state = (const float*)d_in[0];
    const float* k1w   = (const float*)d_in[1];
    const float* b1    = (const float*)d_in[2];
    const float* k2w   = (const float*)d_in[3];
    const float* b2    = (const float*)d_in[4];
    const float* k3w   = (const float*)d_in[5];
    const float* b3    = (const float*)d_in[6];
    const float* W     = (const float*)d_in[7];
    const float* bd    = (const float*)d_in[8];
    float* out = (float*)d_out;

    block1_kernel<<<(BB * L1C * CH1 + 255) / 256, 256>>>(state, k1w, b1);
    fused23_kernel<<<dim3(64, NLC, ZB), 128>>>(k2w, b2, k3w, b3, W, bd, out);
}